// round 6
// baseline (speedup 1.0000x reference)
#include <cuda_runtime.h>
#include <cuda_bf16.h>

// Problem constants
#define BATCH   32768
#define D       768          // 3*16*16 compressed features per sample
#define D4      192          // D/4
#define ROWS_PER_BLOCK 16
#define NBLOCKS (BATCH / ROWS_PER_BLOCK)   // 2048
#define TP 17                // padded P-stride for T (bank-conflict-free)

// ---------------------------------------------------------------------------
// Fused kernel: each block folds lhs/rhs/W into W_eff (two-stage, ~144
// FMA/thread), then streams 16 rows of x doing out[n] = <x[n,:], W_eff> + b.
// 2048 blocks so the DRAM stream has full chip-level parallelism; the
// redundant per-block fold (~75M FMA chip-wide, W re-read from L2) hides
// under the HBM-bound stream of other resident blocks.
// ---------------------------------------------------------------------------
__global__ __launch_bounds__(256)
void fused_kernel(const float4* __restrict__ x,    // [BATCH * D4]
                  const float*  __restrict__ lhs,  // [2,16,8]
                  const float*  __restrict__ rhs,  // [2,8,16]
                  const float*  __restrict__ W,    // [3072]
                  const float*  __restrict__ bptr, // [1]
                  float*        __restrict__ out)  // [BATCH]
{
    __shared__ float sLhs[256];
    __shared__ float sRhs[256];
    __shared__ float sT[96 * TP];        // [ch*2+r][c][q] x P (padded)
    __shared__ float sw[D];              // folded W_eff

    const int t = threadIdx.x;

    sLhs[t] = lhs[t];
    sRhs[t] = rhs[t];
    __syncthreads();

    // ---- Fold stage 1: T[ch,r,c,q,P] = sum_Q rhs[c,q,Q] * W[...] ----
    #pragma unroll
    for (int i = 0; i < 6; i++) {
        const int idx = t + 256 * i;     // 0..1535
        const int P  = idx & 15;
        const int q  = (idx >> 4) & 7;
        const int c  = (idx >> 7) & 1;
        const int r  = (idx >> 8) & 1;
        const int ch = idx >> 9;
        const float* __restrict__ wrow = W + ch * 1024 + (r * 16 + P) * 32 + c * 16;
        const float* __restrict__ rrow = sRhs + c * 128 + q * 16;
        float s = 0.f;
        #pragma unroll
        for (int Q = 0; Q < 16; Q++)
            s = fmaf(rrow[Q], wrow[Q], s);
        sT[(((ch * 2 + r) * 2 + c) * 8 + q) * TP + P] = s;
    }
    __syncthreads();

    // ---- Fold stage 2: Weff[o] = sum_P lhs[r,P,p] * T[ch,r,c,q,P] ----
    #pragma unroll
    for (int i = 0; i < 3; i++) {
        const int o   = t + 256 * i;     // 0..767
        const int ch  = o >> 8;
        const int rem = o & 255;
        const int rr  = rem >> 4;
        const int cc  = rem & 15;
        const int r   = rr >> 3;
        const int p   = rr & 7;
        const int c   = cc >> 3;
        const int q   = cc & 7;
        const float* __restrict__ trow = sT + (((ch * 2 + r) * 2 + c) * 8 + q) * TP;
        const float* __restrict__ lcol = sLhs + r * 128 + p;
        float s = 0.f;
        #pragma unroll
        for (int P = 0; P < 16; P++)
            s = fmaf(lcol[P * 8], trow[P], s);
        sw[o] = s;
    }
    __syncthreads();

    // ---- GEMV: 8 warps x 2 rows = 16 rows per block (R3 structure) ----
    const int warp = t >> 5;
    const int lane = t & 31;
    const int row0 = blockIdx.x * ROWS_PER_BLOCK + warp * 2;
    const float4* __restrict__ w4 = reinterpret_cast<const float4*>(sw);

    const float4* __restrict__ xr0 = x + (size_t)row0 * D4;
    const float4* __restrict__ xr1 = xr0 + D4;

    float a0 = 0.f, a1 = 0.f;
    #pragma unroll
    for (int k = 0; k < 6; k++) {
        const float4 v0 = __ldcs(&xr0[lane + k * 32]);
        const float4 v1 = __ldcs(&xr1[lane + k * 32]);
        const float4 w  = w4[lane + k * 32];
        a0 = fmaf(v0.x, w.x, a0);
        a0 = fmaf(v0.y, w.y, a0);
        a0 = fmaf(v0.z, w.z, a0);
        a0 = fmaf(v0.w, w.w, a0);
        a1 = fmaf(v1.x, w.x, a1);
        a1 = fmaf(v1.y, w.y, a1);
        a1 = fmaf(v1.z, w.z, a1);
        a1 = fmaf(v1.w, w.w, a1);
    }

    #pragma unroll
    for (int off = 16; off > 0; off >>= 1) {
        a0 += __shfl_xor_sync(0xFFFFFFFFu, a0, off);
        a1 += __shfl_xor_sync(0xFFFFFFFFu, a1, off);
    }

    if (lane == 0) {
        const float bb = bptr[0];
        out[row0]     = a0 + bb;
        out[row0 + 1] = a1 + bb;
    }
}

// ---------------------------------------------------------------------------
extern "C" void kernel_launch(void* const* d_in, const int* in_sizes, int n_in,
                              void* d_out, int out_size)
{
    const float* x   = (const float*)d_in[0];   // [32768, 3, 16, 16]
    const float* lhs = (const float*)d_in[1];   // [2, 16, 8]
    const float* rhs = (const float*)d_in[2];   // [2, 8, 16]
    const float* W   = (const float*)d_in[3];   // [1, 3072]
    const float* b   = (const float*)d_in[4];   // [1]
    float* out       = (float*)d_out;           // [32768]

    fused_kernel<<<NBLOCKS, 256>>>((const float4*)x, lhs, rhs, W, b, out);
}

// round 8
// speedup vs baseline: 6.4154x; 6.4154x over previous
#include <cuda_runtime.h>
#include <cuda_bf16.h>

// Problem constants
#define BATCH   32768
#define D       768          // 3*16*16 compressed features per sample
#define D4      192          // D/4

__device__ float g_weff[D];

// ---------------------------------------------------------------------------
// Kernel 1: fold lhs/rhs/W into W_eff[768]. One block per output element.
// Signals programmatic completion as soon as its value is written.
// ---------------------------------------------------------------------------
__global__ void fold_weff_kernel(const float* __restrict__ lhs,   // [2,16,8]
                                 const float* __restrict__ rhs,   // [2,8,16]
                                 const float* __restrict__ W)     // [3072]
{
    const int o   = blockIdx.x;          // 0..767
    const int ch  = o >> 8;
    const int rem = o & 255;
    const int rr  = rem >> 4;
    const int cc  = rem & 15;
    const int r   = rr >> 3;
    const int p   = rr & 7;
    const int c   = cc >> 3;
    const int q   = cc & 7;

    const int t = threadIdx.x;           // 0..255
    const int P = t >> 4;
    const int Q = t & 15;

    float term = lhs[r * 128 + P * 8 + p]
               * rhs[c * 128 + q * 16 + Q]
               * W[ch * 1024 + (r * 16 + P) * 32 + (c * 16 + Q)];

    #pragma unroll
    for (int off = 16; off > 0; off >>= 1)
        term += __shfl_xor_sync(0xFFFFFFFFu, term, off);

    __shared__ float warp_sums[8];
    const int lane = t & 31;
    const int wid  = t >> 5;
    if (lane == 0) warp_sums[wid] = term;
    __syncthreads();

    if (t == 0) {
        float s = 0.f;
        #pragma unroll
        for (int w = 0; w < 8; w++) s += warp_sums[w];
        g_weff[o] = s;
    }
#if __CUDA_ARCH__ >= 900
    cudaTriggerProgrammaticLaunchCompletion();
#endif
}

// ---------------------------------------------------------------------------
// Kernel 2 (PDL secondary): out[n] = dot(x[n,:], W_eff) + b.
// 8 warps x 2 rows = 16 rows/block. All 12 x loads issued BEFORE the grid
// dependency sync (independent of W_eff) -> overlap fold tail + maximize MLP.
// ---------------------------------------------------------------------------
__global__ __launch_bounds__(256)
void gemv_pdl_kernel(const float4* __restrict__ x,    // [BATCH * D4]
                     const float*  __restrict__ bptr, // [1]
                     float*        __restrict__ out)  // [BATCH]
{
    const int t    = threadIdx.x;
    const int warp = t >> 5;
    const int lane = t & 31;
    const int row0 = (blockIdx.x * 8 + warp) * 2;

    const float4* __restrict__ xr0 = x + (size_t)row0 * D4;
    const float4* __restrict__ xr1 = xr0 + D4;

    // x loads do not depend on the fold — issue them all up front.
    float4 v0[6], v1[6];
    #pragma unroll
    for (int k = 0; k < 6; k++) v0[k] = __ldcs(&xr0[lane + k * 32]);
    #pragma unroll
    for (int k = 0; k < 6; k++) v1[k] = __ldcs(&xr1[lane + k * 32]);

#if __CUDA_ARCH__ >= 900
    cudaGridDependencySynchronize();     // fold's g_weff now visible
#endif

    const float4* __restrict__ w4 = reinterpret_cast<const float4*>(g_weff);

    float a0 = 0.f, a1 = 0.f;
    #pragma unroll
    for (int k = 0; k < 6; k++) {
        const float4 w = __ldg(&w4[lane + k * 32]);   // L1/L2-hot, broadcast
        a0 = fmaf(v0[k].x, w.x, a0);
        a0 = fmaf(v0[k].y, w.y, a0);
        a0 = fmaf(v0[k].z, w.z, a0);
        a0 = fmaf(v0[k].w, w.w, a0);
        a1 = fmaf(v1[k].x, w.x, a1);
        a1 = fmaf(v1[k].y, w.y, a1);
        a1 = fmaf(v1[k].z, w.z, a1);
        a1 = fmaf(v1[k].w, w.w, a1);
    }

    #pragma unroll
    for (int off = 16; off > 0; off >>= 1) {
        a0 += __shfl_xor_sync(0xFFFFFFFFu, a0, off);
        a1 += __shfl_xor_sync(0xFFFFFFFFu, a1, off);
    }

    if (lane == 0) {
        const float bb = bptr[0];
        out[row0]     = a0 + bb;
        out[row0 + 1] = a1 + bb;
    }
}

// ---------------------------------------------------------------------------
extern "C" void kernel_launch(void* const* d_in, const int* in_sizes, int n_in,
                              void* d_out, int out_size)
{
    const float* x   = (const float*)d_in[0];   // [32768, 3, 16, 16]
    const float* lhs = (const float*)d_in[1];   // [2, 16, 8]
    const float* rhs = (const float*)d_in[2];   // [2, 8, 16]
    const float* W   = (const float*)d_in[3];   // [1, 3072]
    const float* b   = (const float*)d_in[4];   // [1]
    float* out       = (float*)d_out;           // [32768]

    // Primary: fold kernel (768 blocks x 256 threads)
    fold_weff_kernel<<<D, 256>>>(lhs, rhs, W);

    // Secondary: gemv with programmatic dependent launch (overlaps fold tail)
    cudaLaunchConfig_t cfg = {};
    cfg.gridDim  = dim3(BATCH / 16);   // 2048
    cfg.blockDim = dim3(256);
    cfg.dynamicSmemBytes = 0;
    cfg.stream = 0;                    // same (capture) stream as the fold

    cudaLaunchAttribute attrs[1];
    attrs[0].id = cudaLaunchAttributeProgrammaticStreamSerialization;
    attrs[0].val.programmaticStreamSerializationAllowed = 1;
    cfg.attrs    = attrs;
    cfg.numAttrs = 1;

    cudaLaunchKernelEx(&cfg, gemv_pdl_kernel,
                       (const float4*)x, (const float*)b, (float*)out);
}